// round 7
// baseline (speedup 1.0000x reference)
#include <cuda_runtime.h>
#include <cuda_fp16.h>
#include <math.h>

// ---------------------------------------------------------------------------
// Problem constants
// ---------------------------------------------------------------------------
#define B_    8
#define CIN   256
#define MID   128
#define Hh    128
#define Ww    256
#define Kk    19
#define HW    (Hh*Ww)          // 32768
#define EPSBN 1e-5f
#define HP    (Hh+2)           // 130
#define WP    (Ww+2)           // 258

// ---------------------------------------------------------------------------
// Scratch (device globals: allocation-free)
// ---------------------------------------------------------------------------
__device__ __half g_ft[(size_t)B_ * HP * WP * CIN];  // fp16 NHWC padded
__device__ __half g_w1h[9 * MID * CIN];              // fp16 [(dy*8+cc)*3+dx][mid][32]
__device__ __half g_w2h[80 * MID];                   // fp16 w2 padded to 80 rows
__device__ __half g_xh[(size_t)B_ * HW * MID];       // fp16 x [b][pixel][mid]
__device__ float  g_g[(size_t)B_ * Kk * HW * 4];     // guidance [b][k][hw][4]

// ---------------------------------------------------------------------------
// Helpers
// ---------------------------------------------------------------------------
static __device__ __forceinline__ unsigned smem_u32(const void* p) {
    unsigned r;
    asm("{ .reg .u64 t; cvta.to.shared.u64 t, %1; cvt.u32.u64 %0, t; }"
        : "=r"(r) : "l"(p));
    return r;
}

static __device__ __forceinline__ void cp16(unsigned saddr, const void* gptr) {
    asm volatile("cp.async.cg.shared.global [%0], [%1], 16;"
                 :: "r"(saddr), "l"(gptr));
}

static __device__ __forceinline__ void ldsm4(unsigned* r, unsigned addr) {
    asm volatile("ldmatrix.sync.aligned.m8n8.x4.shared.b16 {%0,%1,%2,%3}, [%4];"
        : "=r"(r[0]), "=r"(r[1]), "=r"(r[2]), "=r"(r[3]) : "r"(addr));
}

static __device__ __forceinline__ void mma16816(float* c, const unsigned* a,
                                                const unsigned* b) {
    asm volatile(
        "mma.sync.aligned.m16n8k16.row.col.f32.f16.f16.f32 "
        "{%0,%1,%2,%3}, {%4,%5,%6,%7}, {%8,%9}, {%0,%1,%2,%3};"
        : "+f"(c[0]), "+f"(c[1]), "+f"(c[2]), "+f"(c[3])
        : "r"(a[0]), "r"(a[1]), "r"(a[2]), "r"(a[3]), "r"(b[0]), "r"(b[1]));
}

// swizzled offset within a 64B-row tile: 4 chunks of 16B per row
static __device__ __forceinline__ unsigned swz64(int row, int ch) {
    return row * 64 + ((ch ^ ((row >> 1) & 3)) << 4);
}

// ---------------------------------------------------------------------------
// Kernel T1: feats NCHW -> padded NHWC fp16. grid (HP, B), block (32,8)
// ---------------------------------------------------------------------------
__global__ __launch_bounds__(256) void transpose_pad_kernel(
    const float* __restrict__ feats)
{
    __shared__ float t[32][33];
    const int tx = threadIdx.x, ty = threadIdx.y;
    const int tid = ty * 32 + tx;
    const int hp = blockIdx.x, b = blockIdx.y;
    __half* orow = g_ft + ((size_t)(b * HP + hp) * WP) * CIN;

    if (hp == 0 || hp == HP - 1) {
        for (int idx = tid; idx < WP * CIN; idx += 256)
            orow[idx] = __float2half(0.f);
        return;
    }
    if (tid < 256) {
        orow[tid] = __float2half(0.f);
        orow[(WP - 1) * CIN + tid] = __float2half(0.f);
    }

    const int h = hp - 1;
    for (int wt = 0; wt < 8; wt++) {
        for (int ct = 0; ct < 8; ct++) {
            const int w0 = wt * 32, c0 = ct * 32;
            __syncthreads();
#pragma unroll
            for (int j = 0; j < 4; j++) {
                int ci = c0 + ty + j * 8;
                t[ty + j * 8][tx] =
                    feats[(((size_t)b * CIN + ci) * Hh + h) * Ww + w0 + tx];
            }
            __syncthreads();
#pragma unroll
            for (int j = 0; j < 4; j++) {
                int w = w0 + ty + j * 8;
                orow[(size_t)(w + 1) * CIN + c0 + tx] =
                    __float2half_rn(t[tx][ty + j * 8]);
            }
        }
    }
}

// ---------------------------------------------------------------------------
// Kernel T2: w1 -> fp16 g_w1h[(((dy*8+cc)*3+dx)*128 + mid)*32 + cw]
// ---------------------------------------------------------------------------
__global__ __launch_bounds__(256) void prep_w1h_kernel(const float* __restrict__ w1)
{
    int idx = blockIdx.x * 256 + threadIdx.x;
    if (idx >= 9 * MID * CIN) return;
    int cw = idx & 31;
    int m  = (idx >> 5) & 127;
    int rest = idx >> 12;           // (dy*8+cc)*3 + dx
    int dx = rest % 3, q = rest / 3;
    int cc = q & 7, dy = q >> 3;
    int ci = cc * 32 + cw;
    g_w1h[idx] = __float2half_rn(w1[(((size_t)m * CIN + ci) * 3 + dy) * 3 + dx]);
}

// Kernel T3: w2 -> fp16, padded to 80 output rows
__global__ __launch_bounds__(256) void prep_w2h_kernel(const float* __restrict__ w2)
{
    int idx = blockIdx.x * 256 + threadIdx.x;
    if (idx >= 80 * MID) return;
    int n = idx >> 7, m = idx & 127;
    float v = (n < 76) ? w2[n * MID + m] : 0.f;
    g_w2h[idx] = __float2half_rn(v);
}

// ---------------------------------------------------------------------------
// Kernel G: conv3x3 fp16 mma implicit GEMM, 512 threads (16 warps, 4/SMSP).
// Per CTA one (b,h) row: M=256 px, N=128 mid, K=2304.
// Warp grid 4(m) x 4(n); warp tile 64 px x 32 mid.
// Stage t=(dy,cc32), 24 stages, 4-deep cp.async ring.
// ---------------------------------------------------------------------------
#define A_ST   16512                 // 258*64
#define B_ST   24576                 // 3*128*64
#define STG    (A_ST + B_ST)         // 41088
#define NSTG   4
#define CSMEM  (NSTG * STG)          // 164352

__global__ void __launch_bounds__(512) conv3x3_mma_kernel(
    const float* __restrict__ gamma, const float* __restrict__ beta,
    const float* __restrict__ mean,  const float* __restrict__ var)
{
    extern __shared__ __align__(1024) unsigned char smem_raw[];
    const unsigned sbase = smem_u32(smem_raw);
    const int tid = threadIdx.x;
    const int L = tid & 31, wid = tid >> 5;
    const int h = blockIdx.x, b = blockIdx.y;
    const int p0w = (wid >> 2) * 64;     // warp m-offset (pixels)
    const int n0w = (wid & 3) * 32;      // warp n-offset (mid)

    // lane-invariant ldsm address pieces
    const int aL = L & 15, aH = L >> 4;
    const int bR = ((L >> 4) << 3) + (L & 7), bH = (L >> 3) & 1;

    auto issue_loads = [&](int t, int buf) {
        const int dy = t >> 3, cc = t & 7;
        const unsigned Ab = sbase + buf * STG;
        const unsigned Bb = Ab + A_ST;
        const __half* asrc = g_ft + ((size_t)(b * HP + h + dy) * WP) * CIN + cc * 32;
#pragma unroll
        for (int i = 0; i < 3; i++) {            // A: 258 rows x 4 chunks = 1032
            int g = tid + i * 512;
            if (g < 1032) {
                int row = g >> 2, c = g & 3;
                cp16(Ab + swz64(row, c), asrc + (size_t)row * CIN + c * 8);
            }
        }
        const __half* bsrc = g_w1h + (size_t)((dy * 8 + cc) * 3) * MID * 32;
#pragma unroll
        for (int i = 0; i < 3; i++) {            // B: 3 x 128 rows x 4 chunks = 1536
            int g = tid + i * 512;
            int dxi = g >> 9, row = (g >> 2) & 127, c = g & 3;
            cp16(Bb + dxi * 8192 + swz64(row, c),
                 bsrc + (size_t)dxi * MID * 32 + row * 32 + c * 8);
        }
        asm volatile("cp.async.commit_group;");
    };

    float acc[4][4][4];
#pragma unroll
    for (int mi = 0; mi < 4; mi++)
#pragma unroll
        for (int ni = 0; ni < 4; ni++)
#pragma unroll
            for (int q = 0; q < 4; q++) acc[mi][ni][q] = 0.f;

    issue_loads(0, 0);
    issue_loads(1, 1);
    issue_loads(2, 2);

    for (int t = 0; t < 24; t++) {
        const int buf = t & (NSTG - 1);
        if (t < 22)       asm volatile("cp.async.wait_group 2;");
        else if (t == 22) asm volatile("cp.async.wait_group 1;");
        else              asm volatile("cp.async.wait_group 0;");
        __syncthreads();
        if (t < 21) issue_loads(t + 3, (t + 3) & (NSTG - 1));

        const unsigned Ab = sbase + buf * STG;
        const unsigned Bb = Ab + A_ST;
#pragma unroll
        for (int dx = 0; dx < 3; dx++) {
#pragma unroll
            for (int kk = 0; kk < 2; kk++) {
                unsigned a[4][4], bf[2][4];
#pragma unroll
                for (int mi = 0; mi < 4; mi++) {
                    int row = p0w + mi * 16 + aL + dx;
                    ldsm4(a[mi], Ab + swz64(row, 2 * kk + aH));
                }
#pragma unroll
                for (int jj = 0; jj < 2; jj++) {
                    int row = n0w + jj * 16 + bR;
                    ldsm4(bf[jj], Bb + dx * 8192 + swz64(row, 2 * kk + bH));
                }
#pragma unroll
                for (int mi = 0; mi < 4; mi++)
#pragma unroll
                    for (int ni = 0; ni < 4; ni++)
                        mma16816(acc[mi][ni], a[mi],
                                 &bf[ni >> 1][(ni & 1) << 1]);
            }
        }
    }

    // Epilogue: BN + ReLU -> g_xh[b][pixel][mid] fp16
    const int midb = n0w + ((L & 3) << 1);
    float iv0[4], iv1[4], bb0[4], bb1[4];
#pragma unroll
    for (int ni = 0; ni < 4; ni++) {
        int m0 = midb + ni * 8;
        iv0[ni] = gamma[m0]     * rsqrtf(var[m0]     + EPSBN);
        iv1[ni] = gamma[m0 + 1] * rsqrtf(var[m0 + 1] + EPSBN);
        bb0[ni] = beta[m0]     - mean[m0]     * iv0[ni];
        bb1[ni] = beta[m0 + 1] - mean[m0 + 1] * iv1[ni];
    }
#pragma unroll
    for (int mi = 0; mi < 4; mi++) {
        int p0 = p0w + mi * 16 + (L >> 2);
        __half* o = g_xh + ((size_t)b * HW + (size_t)h * Ww + p0) * MID;
#pragma unroll
        for (int ni = 0; ni < 4; ni++) {
            int m0 = midb + ni * 8;
            float u0 = fmaxf(fmaf(acc[mi][ni][0], iv0[ni], bb0[ni]), 0.f);
            float u1 = fmaxf(fmaf(acc[mi][ni][1], iv1[ni], bb1[ni]), 0.f);
            float u2 = fmaxf(fmaf(acc[mi][ni][2], iv0[ni], bb0[ni]), 0.f);
            float u3 = fmaxf(fmaf(acc[mi][ni][3], iv1[ni], bb1[ni]), 0.f);
            *(__half2*)(o + m0)           = __floats2half2_rn(u0, u1);
            *(__half2*)(o + 8 * MID + m0) = __floats2half2_rn(u2, u3);
        }
    }
}

// ---------------------------------------------------------------------------
// Kernel 2: conv1x1 as fp16 mma GEMM + bias + softmax over 4 dirs.
// ---------------------------------------------------------------------------
#define C1_A   65536                 // 256 rows x 256B
#define C1_B   20480                 // 80 rows x 256B
#define C1SMEM (C1_A + C1_B)

static __device__ __forceinline__ unsigned swz256(int row, int ch) {
    return row * 256 + ((ch & 8) << 4) + (((ch & 7) ^ (row & 7)) << 4);
}

__global__ void __launch_bounds__(256) conv1x1_mma_softmax_kernel(
    const float* __restrict__ b2)
{
    extern __shared__ __align__(1024) unsigned char smem_raw[];
    const unsigned sA = smem_u32(smem_raw);
    const unsigned sB = sA + C1_A;
    const int tid = threadIdx.x;
    const int L = tid & 31, wid = tid >> 5;
    const int p0 = blockIdx.x * 256, b = blockIdx.y;

    const __half* xsrc = g_xh + ((size_t)b * HW + p0) * MID;
#pragma unroll
    for (int i = 0; i < 16; i++) {               // A: 256 rows x 16 chunks
        int g = tid + i * 256;
        int row = g >> 4, c = g & 15;
        cp16(sA + swz256(row, c), xsrc + (size_t)row * MID + c * 8);
    }
#pragma unroll
    for (int i = 0; i < 5; i++) {                // B: 80 rows x 16 chunks
        int g = tid + i * 256;
        int row = g >> 4, c = g & 15;
        cp16(sB + swz256(row, c), g_w2h + (size_t)row * MID + c * 8);
    }
    asm volatile("cp.async.commit_group;");
    asm volatile("cp.async.wait_group 0;");
    __syncthreads();

    const int pw = wid * 32;
    float acc[2][10][4];
#pragma unroll
    for (int mi = 0; mi < 2; mi++)
#pragma unroll
        for (int ni = 0; ni < 10; ni++)
#pragma unroll
            for (int q = 0; q < 4; q++) acc[mi][ni][q] = 0.f;

#pragma unroll
    for (int kk = 0; kk < 8; kk++) {
        unsigned a[2][4], bf[5][4];
#pragma unroll
        for (int mi = 0; mi < 2; mi++) {
            int row = pw + mi * 16 + (L & 15);
            ldsm4(a[mi], sA + swz256(row, 2 * kk + (L >> 4)));
        }
#pragma unroll
        for (int jj = 0; jj < 5; jj++) {
            int row = jj * 16 + ((L >> 4) << 3) + (L & 7);
            ldsm4(bf[jj], sB + swz256(row, 2 * kk + ((L >> 3) & 1)));
        }
#pragma unroll
        for (int mi = 0; mi < 2; mi++)
#pragma unroll
            for (int ni = 0; ni < 10; ni++)
                mma16816(acc[mi][ni], a[mi], &bf[ni >> 1][(ni & 1) << 1]);
    }

    const int d0 = (L & 1) * 2;
#pragma unroll
    for (int mi = 0; mi < 2; mi++) {
#pragma unroll
        for (int h2 = 0; h2 < 2; h2++) {
            int px = p0 + pw + mi * 16 + (L >> 2) + h2 * 8;
#pragma unroll
            for (int ni = 0; ni < 10; ni++) {
                int n0 = 8 * ni + 2 * (L & 3);
                bool valid = (n0 < 76);
                float bb0 = valid ? b2[n0] : 0.f;
                float bb1 = valid ? b2[n0 + 1] : 0.f;
                float v0 = acc[mi][ni][2 * h2]     + bb0;
                float v1 = acc[mi][ni][2 * h2 + 1] + bb1;
                float p0v = __shfl_xor_sync(0xFFFFFFFFu, v0, 1);
                float p1v = __shfl_xor_sync(0xFFFFFFFFu, v1, 1);
                float mx = fmaxf(fmaxf(v0, v1), fmaxf(p0v, p1v));
                float e0 = expf(v0 - mx), e1 = expf(v1 - mx);
                float ep0 = expf(p0v - mx), ep1 = expf(p1v - mx);
                float inv = 1.f / (e0 + e1 + ep0 + ep1);
                if (valid) {
                    int k = n0 >> 2;
                    float2 r; r.x = e0 * inv; r.y = e1 * inv;
                    *(float2*)(g_g + (((size_t)b * Kk + k) * HW + px) * 4 + d0) = r;
                }
            }
        }
    }
}

// ---------------------------------------------------------------------------
// Kernel 3: all 4 propagation steps fused; 32x32 output tile + halo 4.
// ---------------------------------------------------------------------------
#define TR 40                         // loaded region 40x40

template<int S>
static __device__ __forceinline__ void prop_step_smem(
    const float* __restrict__ src, float* __restrict__ dst,
    const float* __restrict__ sg, int tid)
{
    const int n = TR - 2 * S;
    for (int q = tid; q < n * n; q += 256) {
        int r = S + q / n, c = S + q % n;
        int id = r * TR + c;
        float4 gv = *(const float4*)(sg + id * 4);
        float hc = src[id];
        float l = src[id - 1], rr = src[id + 1];
        float u = src[id - TR], d = src[id + TR];
        float selfw = 1.f - (gv.x + gv.y + gv.z + gv.w);
        dst[id] = selfw * hc + gv.x * l + gv.y * rr + gv.z * u + gv.w * d;
    }
}

__global__ __launch_bounds__(256) void prop_fused_kernel(
    const float* __restrict__ logits, float* __restrict__ h_out)
{
    __shared__ float sg[TR * TR * 4];
    __shared__ float sh[2][TR * TR];

    const int tid = threadIdx.x;
    const int wo = blockIdx.x * 32, ho = blockIdx.y * 32;
    const int plane = blockIdx.z;
    const float* hsrc = logits + (size_t)plane * HW;
    const float* gsrc = g_g + (size_t)plane * HW * 4;

    for (int q = tid; q < TR * TR; q += 256) {
        int r = q / TR, c = q % TR;
        int gr = ho + r - 4, gc = wo + c - 4;
        bool in = ((unsigned)gr < (unsigned)Hh) && ((unsigned)gc < (unsigned)Ww);
        float4 gv = make_float4(0.f, 0.f, 0.f, 0.f);
        float hv = 0.f;
        if (in) {
            gv = *(const float4*)(gsrc + ((size_t)gr * Ww + gc) * 4);
            hv = hsrc[(size_t)gr * Ww + gc];
        }
        *(float4*)(sg + q * 4) = gv;
        sh[0][q] = hv;
    }
    __syncthreads();

    prop_step_smem<1>(sh[0], sh[1], sg, tid);
    __syncthreads();
    prop_step_smem<2>(sh[1], sh[0], sg, tid);
    __syncthreads();
    prop_step_smem<3>(sh[0], sh[1], sg, tid);
    __syncthreads();

    const float* src = sh[1];
    for (int q = tid; q < 32 * 32; q += 256) {
        int r = 4 + (q >> 5), c = 4 + (q & 31);
        int id = r * TR + c;
        float4 gv = *(const float4*)(sg + id * 4);
        float hc = src[id];
        float l = src[id - 1], rr = src[id + 1];
        float u = src[id - TR], d = src[id + TR];
        float selfw = 1.f - (gv.x + gv.y + gv.z + gv.w);
        float res = selfw * hc + gv.x * l + gv.y * rr + gv.z * u + gv.w * d;
        h_out[(size_t)plane * HW + (size_t)(ho + r - 4) * Ww + (wo + c - 4)] = res;
    }
}

// ---------------------------------------------------------------------------
// kernel_launch
// inputs: 0 feats, 1 logits, 2 w1, 3 gamma, 4 beta, 5 mean, 6 var, 7 w2, 8 b2
// ---------------------------------------------------------------------------
extern "C" void kernel_launch(void* const* d_in, const int* in_sizes, int n_in,
                              void* d_out, int out_size)
{
    const float* feats  = (const float*)d_in[0];
    const float* logits = (const float*)d_in[1];
    const float* w1     = (const float*)d_in[2];
    const float* gamma  = (const float*)d_in[3];
    const float* beta   = (const float*)d_in[4];
    const float* mean   = (const float*)d_in[5];
    const float* var    = (const float*)d_in[6];
    const float* w2     = (const float*)d_in[7];
    const float* b2     = (const float*)d_in[8];
    float* out = (float*)d_out;

    cudaFuncSetAttribute(conv3x3_mma_kernel,
                         cudaFuncAttributeMaxDynamicSharedMemorySize, CSMEM);
    cudaFuncSetAttribute(conv1x1_mma_softmax_kernel,
                         cudaFuncAttributeMaxDynamicSharedMemorySize, C1SMEM);

    transpose_pad_kernel<<<dim3(HP, B_), dim3(32, 8)>>>(feats);
    prep_w1h_kernel<<<(9 * MID * CIN + 255) / 256, 256>>>(w1);
    prep_w2h_kernel<<<(80 * MID + 255) / 256, 256>>>(w2);
    conv3x3_mma_kernel<<<dim3(Hh, B_), 512, CSMEM>>>(gamma, beta, mean, var);
    conv1x1_mma_softmax_kernel<<<dim3(HW / 256, B_), 256, C1SMEM>>>(b2);
    prop_fused_kernel<<<dim3(Ww / 32, Hh / 32, B_ * Kk), 256>>>(logits, out);
}